// round 2
// baseline (speedup 1.0000x reference)
#include <cuda_runtime.h>
#include <math.h>

// Problem constants
#define LDIM   8192
#define DDIM   512
#define BATCH  8
#define MDIM   1024   // 2*D output channels of GEMM
#define KDIM   512

// Scratch (device globals: allocation-free per harness rules)
__device__ float g_Wn[MDIM * KDIM];                       // 2 MiB
__device__ float g_fb[(size_t)BATCH * MDIM * LDIM];       // 256 MiB

// ---------------------------------------------------------------------------
// Kernel 1: weight normalization. One block per output row.
// Wn[o,i] = W[o,i] / ((1e-4 + ||W_o||/sqrt(512)) * sqrt(512))
// ---------------------------------------------------------------------------
__global__ __launch_bounds__(128) void wnorm_kernel(const float* __restrict__ W) {
    int o = blockIdx.x;
    const float* w = W + (size_t)o * KDIM;
    __shared__ float red[128];
    float s = 0.f;
    #pragma unroll
    for (int i = threadIdx.x; i < KDIM; i += 128) {
        float v = w[i];
        s = fmaf(v, v, s);
    }
    red[threadIdx.x] = s;
    __syncthreads();
    for (int st = 64; st > 0; st >>= 1) {
        if (threadIdx.x < st) red[threadIdx.x] += red[threadIdx.x + st];
        __syncthreads();
    }
    float norm = sqrtf(red[0]);
    const float sq = 22.627416997969522f;  // sqrt(512)
    float inv = 1.f / ((1e-4f + norm / sq) * sq);
    #pragma unroll
    for (int i = threadIdx.x; i < KDIM; i += 128)
        g_Wn[(size_t)o * KDIM + i] = w[i] * inv;
}

// ---------------------------------------------------------------------------
// Kernel 2: fp32 SIMT GEMM. fb[b,o,l] = sum_i Wn[o,i] * x[b,i,l]
// Block tile 128(M) x 128(N), BK=8, 256 threads, 8x8 per-thread microtile,
// register prefetch of next global tile to hide L2 latency.
// Grid: (L/128=64, M/128=8, B=8). All dims divide exactly -> no bounds checks.
// ---------------------------------------------------------------------------
__global__ __launch_bounds__(256) void gemm_kernel(const float* __restrict__ X) {
    const int b  = blockIdx.z;
    const int m0 = blockIdx.y << 7;
    const int n0 = blockIdx.x << 7;

    __shared__ float As[8][128];   // [k][m]
    __shared__ float Bs[8][128];   // [k][n]

    const int tid = threadIdx.x;
    const int ty = tid >> 4;          // 0..15 (M dim)
    const int tx = tid & 15;          // 0..15 (N dim)

    const int rowA = tid >> 1;        // 0..127
    const int colA = (tid & 1) << 2;  // 0 or 4
    const int rowB = tid >> 5;        // 0..7
    const int colB = (tid & 31) << 2; // 0..124

    const float* Aptr = g_Wn + (size_t)(m0 + rowA) * KDIM + colA;
    const float* Bptr = X + ((size_t)b * DDIM + rowB) * LDIM + n0 + colB;

    float acc[8][8];
    #pragma unroll
    for (int i = 0; i < 8; i++)
        #pragma unroll
        for (int j = 0; j < 8; j++) acc[i][j] = 0.f;

    // prefetch first tile
    float4 a4 = *(const float4*)Aptr;
    float4 b4 = *(const float4*)Bptr;

    for (int k0 = 0; k0 < KDIM; k0 += 8) {
        __syncthreads();
        As[colA + 0][rowA] = a4.x;
        As[colA + 1][rowA] = a4.y;
        As[colA + 2][rowA] = a4.z;
        As[colA + 3][rowA] = a4.w;
        *(float4*)&Bs[rowB][colB] = b4;
        __syncthreads();

        if (k0 + 8 < KDIM) {
            a4 = *(const float4*)(Aptr + k0 + 8);
            b4 = *(const float4*)(Bptr + (size_t)(k0 + 8) * LDIM);
        }

        #pragma unroll
        for (int kk = 0; kk < 8; kk++) {
            float4 x0 = *(const float4*)&As[kk][ty << 3];
            float4 x1 = *(const float4*)&As[kk][(ty << 3) + 4];
            float4 y0 = *(const float4*)&Bs[kk][tx << 3];
            float4 y1 = *(const float4*)&Bs[kk][(tx << 3) + 4];
            float ar[8] = {x0.x, x0.y, x0.z, x0.w, x1.x, x1.y, x1.z, x1.w};
            float br[8] = {y0.x, y0.y, y0.z, y0.w, y1.x, y1.y, y1.z, y1.w};
            #pragma unroll
            for (int i = 0; i < 8; i++)
                #pragma unroll
                for (int j = 0; j < 8; j++)
                    acc[i][j] = fmaf(ar[i], br[j], acc[i][j]);
        }
    }

    float* Cp = g_fb + ((size_t)b * MDIM + m0 + (ty << 3)) * LDIM + n0 + (tx << 3);
    #pragma unroll
    for (int i = 0; i < 8; i++) {
        float4 o0 = make_float4(acc[i][0], acc[i][1], acc[i][2], acc[i][3]);
        float4 o1 = make_float4(acc[i][4], acc[i][5], acc[i][6], acc[i][7]);
        *(float4*)(Cp + (size_t)i * LDIM)     = o0;
        *(float4*)(Cp + (size_t)i * LDIM + 4) = o1;
    }
}

// ---------------------------------------------------------------------------
// Pointwise map: given g and h, produce recurrence coeff a and value v.
//   e = exp(-|g|); r = rsqrt(1+e^2)
//   sigmoid(-g)*sqrt(sech(g)+1) = (g>=0 ? e*r : r)   -> coeff a
//   sigmoid(g)*sqrt(sech(g)+1)  = (g>=0 ? r   : e*r) -> value coeff
//   v = value_coeff * sign(h)*max(|h|, 1e-6)
// ---------------------------------------------------------------------------
__device__ __forceinline__ void compute_av(float g, float h, float& a, float& v) {
    float e  = __expf(-fabsf(g));
    float r  = rsqrtf(fmaf(e, e, 1.f));
    float er = e * r;
    float vc;
    if (g >= 0.f) { a = er; vc = r; }
    else          { a = r;  vc = er; }
    float hs = fmaxf(fabsf(h), 1e-6f);
    hs = (h < 0.f) ? -hs : hs;
    v = vc * hs;
}

// ---------------------------------------------------------------------------
// Kernel 3: chunked parallel scan over L=8192 per (batch, channel, direction).
// Block = 256 threads, each thread owns 32 consecutive time steps.
// Row data staged in skewed shared memory (bank-conflict-free strided access).
// Backward rows load/store with reversed time index.
// Affine composition: (A1,S1) then (A2,S2) -> (A1*A2, A2*S1 + S2), h_init = 0.
// ---------------------------------------------------------------------------
#define SKEW_SZ (LDIM + LDIM / 32)   // 8448 floats per array

__global__ __launch_bounds__(256) void scan_kernel(float* __restrict__ out) {
    extern __shared__ float sh[];
    float* sh_h = sh;                 // SKEW_SZ floats
    float* sh_g = sh + SKEW_SZ;       // SKEW_SZ floats
    __shared__ float warpA[8], warpS[8];

    const int row = blockIdx.x;       // 0..4095
    const int b   = row >> 9;
    const int c   = row & 511;
    const bool back = (c >= 256);
    const int ch  = back ? (c - 256) : c;

    const float* hrow = g_fb + ((size_t)b * MDIM + (back ? 512 + ch : ch)) * LDIM;
    const float* grow = g_fb + ((size_t)b * MDIM + (back ? 768 + ch : 256 + ch)) * LDIM;
    float* orow = out + ((size_t)b * DDIM + c) * LDIM;

    const int tid  = threadIdx.x;
    const int lane = tid & 31;
    const int w    = tid >> 5;

    // Load row into smem in scan-time order (reversed for backward rows)
    for (int l = tid; l < LDIM; l += 256) {
        int tau = back ? (LDIM - 1 - l) : l;
        int si = tau + (tau >> 5);
        sh_h[si] = hrow[l];
        sh_g[si] = grow[l];
    }
    __syncthreads();

    // Phase 1: per-thread compose of its 32-step chunk (A = prod a, S = scan value)
    const int base = tid * 33;        // skewed base: tid*32 + tid
    float A = 1.f, S = 0.f;
    #pragma unroll 8
    for (int j = 0; j < 32; j++) {
        float a, v;
        compute_av(sh_g[base + j], sh_h[base + j], a, v);
        S = fmaf(a, S, v);
        A *= a;
    }

    // Warp-level inclusive scan of affine pairs (time order = thread order)
    #pragma unroll
    for (int off = 1; off < 32; off <<= 1) {
        float Ap = __shfl_up_sync(0xffffffffu, A, off);
        float Sp = __shfl_up_sync(0xffffffffu, S, off);
        if (lane >= off) { S = fmaf(A, Sp, S); A *= Ap; }
    }
    if (lane == 31) { warpA[w] = A; warpS[w] = S; }

    // Thread-exclusive within warp (before syncthreads; shuffles are warp-local)
    float Ae = __shfl_up_sync(0xffffffffu, A, 1);
    float Se = __shfl_up_sync(0xffffffffu, S, 1);
    if (lane == 0) { Ae = 1.f; Se = 0.f; }
    __syncthreads();

    // Cross-warp exclusive carry (h value after all previous warps, h_init = 0)
    float carry = 0.f;
    for (int i = 0; i < w; i++) carry = fmaf(warpA[i], carry, warpS[i]);

    // h at the start of this thread's chunk
    float h = fmaf(Ae, carry, Se);

    // Phase 2: recompute chunk with true carry, write results into sh_h
    #pragma unroll 8
    for (int j = 0; j < 32; j++) {
        float a, v;
        compute_av(sh_g[base + j], sh_h[base + j], a, v);
        h = fmaf(a, h, v);
        sh_h[base + j] = h;
    }
    __syncthreads();

    // Coalesced writeback (un-reverse for backward rows)
    for (int l = tid; l < LDIM; l += 256) {
        int tau = back ? (LDIM - 1 - l) : l;
        orow[l] = sh_h[tau + (tau >> 5)];
    }
}

// ---------------------------------------------------------------------------
// Launcher
// ---------------------------------------------------------------------------
extern "C" void kernel_launch(void* const* d_in, const int* in_sizes, int n_in,
                              void* d_out, int out_size) {
    const float* x = (const float*)d_in[0];
    const float* W = (const float*)d_in[1];
    // Defensive: metadata order should be (x, W); swap if sizes say otherwise.
    if (n_in >= 2 && in_sizes[0] == MDIM * KDIM && in_sizes[1] != MDIM * KDIM) {
        W = (const float*)d_in[0];
        x = (const float*)d_in[1];
    }
    float* out = (float*)d_out;

    const int scan_smem = 2 * SKEW_SZ * (int)sizeof(float);  // 67584 B
    cudaFuncSetAttribute(scan_kernel,
                         cudaFuncAttributeMaxDynamicSharedMemorySize, scan_smem);

    wnorm_kernel<<<MDIM, 128>>>(W);
    gemm_kernel<<<dim3(LDIM / 128, MDIM / 128, BATCH), 256>>>(x);
    scan_kernel<<<BATCH * DDIM, 256, scan_smem>>>(out);
}

// round 5
// speedup vs baseline: 2.3907x; 2.3907x over previous
#include <cuda_runtime.h>
#include <cuda_bf16.h>
#include <math.h>
#include <cstdint>

// Problem constants
#define LDIM   8192
#define DDIM   512
#define BATCH  8
#define MDIM   1024
#define KDIM   512

// GEMM tiling (mma.sync path — tcgen05 unavailable: harness PTX target is sm_103, not sm_103a)
#define BM 128
#define BN 128
#define BKC 64                    // bf16 per K-chunk = 128B rows (SW128 swizzle domain)
#define NCHUNK (KDIM / BKC)       // 8
#define STAGES 3
#define ARR_BYTES (128 * 128)     // one operand array per stage: 128 rows x 128B
#define STAGE_BYTES (4 * ARR_BYTES)             // Ah, Al, Bh, Bl
#define GEMM_SMEM (STAGES * STAGE_BYTES + 1024) // 197632 B

// Scratch (device globals: allocation-free per harness rules)
__device__ __nv_bfloat16 g_Wh[MDIM * KDIM];
__device__ __nv_bfloat16 g_Wl[MDIM * KDIM];
__device__ __nv_bfloat16 g_xh[(size_t)BATCH * LDIM * KDIM];   // [b][l][i] K-major
__device__ __nv_bfloat16 g_xl[(size_t)BATCH * LDIM * KDIM];
__device__ float g_fb[(size_t)BATCH * MDIM * LDIM];           // 256 MiB

// ---------------------------------------------------------------------------
// helpers
// ---------------------------------------------------------------------------
__device__ __forceinline__ uint32_t smem_u32(const void* p) {
    uint32_t a;
    asm("{ .reg .u64 t; cvta.to.shared.u64 t, %1; cvt.u32.u64 %0, t; }" : "=r"(a) : "l"(p));
    return a;
}
__device__ __forceinline__ void cp_async16(uint32_t dst, const void* src) {
    asm volatile("cp.async.cg.shared.global [%0], [%1], 16;\n" :: "r"(dst), "l"(src) : "memory");
}
#define CP_COMMIT() asm volatile("cp.async.commit_group;" ::: "memory")
#define CP_WAIT1()  asm volatile("cp.async.wait_group 1;" ::: "memory")

#define LDSM_X4(r0, r1, r2, r3, addr) \
    asm volatile("ldmatrix.sync.aligned.m8n8.x4.shared.b16 {%0,%1,%2,%3}, [%4];" \
        : "=r"(r0), "=r"(r1), "=r"(r2), "=r"(r3) : "r"(addr))

#define MMA16816(d, a, b) \
    asm volatile("mma.sync.aligned.m16n8k16.row.col.f32.bf16.bf16.f32 " \
        "{%0,%1,%2,%3}, {%4,%5,%6,%7}, {%8,%9}, {%0,%1,%2,%3};" \
        : "+f"((d)[0]), "+f"((d)[1]), "+f"((d)[2]), "+f"((d)[3]) \
        : "r"((a)[0]), "r"((a)[1]), "r"((a)[2]), "r"((a)[3]), "r"((b)[0]), "r"((b)[1]))

// ---------------------------------------------------------------------------
// Kernel 1: weight norm -> bf16 hi/lo
// ---------------------------------------------------------------------------
__global__ __launch_bounds__(128) void wnorm_kernel(const float* __restrict__ W) {
    int o = blockIdx.x;
    const float* w = W + (size_t)o * KDIM;
    __shared__ float red[128];
    float s = 0.f;
    for (int i = threadIdx.x; i < KDIM; i += 128) { float v = w[i]; s = fmaf(v, v, s); }
    red[threadIdx.x] = s;
    __syncthreads();
    for (int st = 64; st > 0; st >>= 1) {
        if (threadIdx.x < st) red[threadIdx.x] += red[threadIdx.x + st];
        __syncthreads();
    }
    const float sq = 22.627416997969522f;  // sqrt(512)
    float inv = 1.f / ((1e-4f + sqrtf(red[0]) / sq) * sq);
    for (int i = threadIdx.x; i < KDIM; i += 128) {
        float v = w[i] * inv;
        __nv_bfloat16 h = __float2bfloat16(v);
        __nv_bfloat16 l = __float2bfloat16(v - __bfloat162float(h));
        g_Wh[(size_t)o * KDIM + i] = h;
        g_Wl[(size_t)o * KDIM + i] = l;
    }
}

// ---------------------------------------------------------------------------
// Kernel 2: x [b][i][l] fp32 -> transposed bf16 hi/lo [b][l][i]
// ---------------------------------------------------------------------------
__global__ __launch_bounds__(256) void xconv_kernel(const float* __restrict__ X) {
    __shared__ float sm[32][33];
    const int b = blockIdx.z, i0 = blockIdx.y * 32, l0 = blockIdx.x * 32;
    const int tx = threadIdx.x, ty = threadIdx.y;
    #pragma unroll
    for (int r = 0; r < 4; r++) {
        int i = i0 + ty + r * 8;
        sm[ty + r * 8][tx] = X[((size_t)b * DDIM + i) * LDIM + l0 + tx];
    }
    __syncthreads();
    #pragma unroll
    for (int r = 0; r < 4; r++) {
        int l = l0 + ty + r * 8;
        float v = sm[tx][ty + r * 8];
        __nv_bfloat16 h = __float2bfloat16(v);
        __nv_bfloat16 lo = __float2bfloat16(v - __bfloat162float(h));
        size_t idx = ((size_t)b * LDIM + l) * KDIM + i0 + tx;
        g_xh[idx] = h;
        g_xl[idx] = lo;
    }
}

// ---------------------------------------------------------------------------
// Kernel 3: bf16x3 GEMM via mma.sync m16n8k16.
// fb[b][m][l] = sum_i Wn[m][i] x[b][i][l], C tile 128x128, 3-stage cp.async.
// 8 warps as 2(m) x 4(n); warp tile 64x32.
// B stored [n][k] == col-major B[k][n]: NON-trans ldmatrix gives the exact
// mma B-fragment (lane -> n=l/4, k=(l%4)*2+i).  (R4 bug: .trans swapped k<->n.)
// ---------------------------------------------------------------------------
__global__ __launch_bounds__(256, 1) void gemm_mma_kernel() {
    extern __shared__ char smem[];
    const uint32_t sb = (smem_u32(smem) + 1023u) & ~1023u;
    const int tid = threadIdx.x;
    const int wid = tid >> 5, lane = tid & 31;
    const int m0 = blockIdx.x * BM, n0 = blockIdx.y * BN, b = blockIdx.z;
    const int wm0 = (wid >> 2) * 64;   // warp m offset in CTA tile
    const int wn0 = (wid & 3) * 32;    // warp n offset

    const __nv_bfloat16* Ah = g_Wh + (size_t)m0 * KDIM;
    const __nv_bfloat16* Al = g_Wl + (size_t)m0 * KDIM;
    const __nv_bfloat16* Bh = g_xh + ((size_t)b * LDIM + n0) * KDIM;
    const __nv_bfloat16* Bl = g_xl + ((size_t)b * LDIM + n0) * KDIM;

    // issue one K-chunk (Ah|Al|Bh|Bl, each 128 rows x 128B, xor-swizzled)
    auto issue = [&](int s, int k0) {
        const uint32_t st = sb + s * STAGE_BYTES;
        #pragma unroll
        for (int q = 0; q < 4; q++) {
            int idx = tid + q * 256;
            int row = idx >> 3, seg = idx & 7;
            uint32_t off = (uint32_t)(row * 128) + (uint32_t)((seg ^ (row & 7)) << 4);
            size_t go = (size_t)row * KDIM + k0 + seg * 8;
            cp_async16(st + off,                 Ah + go);
            cp_async16(st + ARR_BYTES + off,     Al + go);
            cp_async16(st + 2 * ARR_BYTES + off, Bh + go);
            cp_async16(st + 3 * ARR_BYTES + off, Bl + go);
        }
        CP_COMMIT();
    };

    float acc[4][4][4];
    #pragma unroll
    for (int i = 0; i < 4; i++)
        #pragma unroll
        for (int j = 0; j < 4; j++)
            #pragma unroll
            for (int k = 0; k < 4; k++) acc[i][j][k] = 0.f;

    issue(0, 0);
    issue(1, BKC);

    // A ldmatrix lane addressing: lanes 0-15 rows m0..15 (seg k), 16-31 same rows (seg k+8)
    const int a_row_in_tile = lane & 15;
    const int a_seg_sel = lane >> 4;
    // B ldmatrix lane addressing (non-trans, matrix order r0=(nL,kL) r1=(nL,kH) r2=(nH,kL) r3=(nH,kH)):
    const int b_n_off   = ((lane >> 4) & 1) * 8 + (lane & 7);
    const int b_seg_sel = (lane >> 3) & 1;

    for (int c = 0; c < NCHUNK; c++) {
        CP_WAIT1();
        __syncthreads();
        if (c + 2 < NCHUNK) issue((c + 2) % STAGES, (c + 2) * BKC);
        else CP_COMMIT();  // empty group keeps wait_group accounting aligned

        const uint32_t sa_h = sb + (c % STAGES) * STAGE_BYTES;
        const uint32_t sa_l = sa_h + ARR_BYTES;
        const uint32_t sbh  = sa_h + 2 * ARR_BYTES;
        const uint32_t sbl  = sa_h + 3 * ARR_BYTES;

        #pragma unroll
        for (int ks = 0; ks < 4; ks++) {
            uint32_t ah[4][4], al[4][4];
            #pragma unroll
            for (int mi = 0; mi < 4; mi++) {
                int row = wm0 + mi * 16 + a_row_in_tile;
                int seg = ks * 2 + a_seg_sel;
                uint32_t off = (uint32_t)(row * 128) + (uint32_t)((seg ^ (row & 7)) << 4);
                LDSM_X4(ah[mi][0], ah[mi][1], ah[mi][2], ah[mi][3], sa_h + off);
                LDSM_X4(al[mi][0], al[mi][1], al[mi][2], al[mi][3], sa_l + off);
            }
            uint32_t bh[4][2], bl[4][2];
            #pragma unroll
            for (int np = 0; np < 2; np++) {
                int n = wn0 + np * 16 + b_n_off;
                int seg = ks * 2 + b_seg_sel;
                uint32_t off = (uint32_t)(n * 128) + (uint32_t)((seg ^ (n & 7)) << 4);
                uint32_t r0, r1, r2, r3;
                LDSM_X4(r0, r1, r2, r3, sbh + off);
                bh[np * 2][0] = r0; bh[np * 2][1] = r1;
                bh[np * 2 + 1][0] = r2; bh[np * 2 + 1][1] = r3;
                LDSM_X4(r0, r1, r2, r3, sbl + off);
                bl[np * 2][0] = r0; bl[np * 2][1] = r1;
                bl[np * 2 + 1][0] = r2; bl[np * 2 + 1][1] = r3;
            }
            #pragma unroll
            for (int mi = 0; mi < 4; mi++)
                #pragma unroll
                for (int ni = 0; ni < 4; ni++) {
                    MMA16816(acc[mi][ni], ah[mi], bh[ni]);
                    MMA16816(acc[mi][ni], ah[mi], bl[ni]);
                    MMA16816(acc[mi][ni], al[mi], bh[ni]);
                }
        }
    }

    // epilogue: direct float2 stores (C frag: c01 row=l/4, c23 row=l/4+8, cols (l%4)*2)
    float* dst = g_fb + ((size_t)b * MDIM + m0) * LDIM + n0;
    const int erow = lane >> 2, ecol = (lane & 3) * 2;
    #pragma unroll
    for (int mi = 0; mi < 4; mi++)
        #pragma unroll
        for (int ni = 0; ni < 4; ni++) {
            int row = wm0 + mi * 16 + erow;
            int col = wn0 + ni * 8 + ecol;
            *(float2*)&dst[(size_t)row * LDIM + col] =
                make_float2(acc[mi][ni][0], acc[mi][ni][1]);
            *(float2*)&dst[(size_t)(row + 8) * LDIM + col] =
                make_float2(acc[mi][ni][2], acc[mi][ni][3]);
        }
}

// ---------------------------------------------------------------------------
// Pointwise recurrence map (exact closed form of the reference's log-space op)
// ---------------------------------------------------------------------------
__device__ __forceinline__ void compute_av(float g, float h, float& a, float& v) {
    float e  = __expf(-fabsf(g));
    float r  = rsqrtf(fmaf(e, e, 1.f));
    float er = e * r;
    float vc;
    if (g >= 0.f) { a = er; vc = r; }
    else          { a = r;  vc = er; }
    float hs = fmaxf(fabsf(h), 1e-6f);
    hs = (h < 0.f) ? -hs : hs;
    v = vc * hs;
}

// ---------------------------------------------------------------------------
// Kernel 4: chunked parallel scan over L per (batch, channel, direction)
// ---------------------------------------------------------------------------
#define SKEW_SZ (LDIM + LDIM / 32)

__global__ __launch_bounds__(256) void scan_kernel(float* __restrict__ out) {
    extern __shared__ float sh[];
    float* sh_h = sh;
    float* sh_g = sh + SKEW_SZ;
    __shared__ float warpA[8], warpS[8];

    const int row = blockIdx.x;
    const int b   = row >> 9;
    const int c   = row & 511;
    const bool back = (c >= 256);
    const int ch  = back ? (c - 256) : c;

    const float* hrow = g_fb + ((size_t)b * MDIM + (back ? 512 + ch : ch)) * LDIM;
    const float* grow = g_fb + ((size_t)b * MDIM + (back ? 768 + ch : 256 + ch)) * LDIM;
    float* orow = out + ((size_t)b * DDIM + c) * LDIM;

    const int tid  = threadIdx.x;
    const int lane = tid & 31;
    const int w    = tid >> 5;

    for (int l = tid; l < LDIM; l += 256) {
        int tau = back ? (LDIM - 1 - l) : l;
        int si = tau + (tau >> 5);
        sh_h[si] = hrow[l];
        sh_g[si] = grow[l];
    }
    __syncthreads();

    // Phase 1: compute (a, v) once (cached into smem), compose chunk
    const int base = tid * 33;
    float A = 1.f, S = 0.f;
    #pragma unroll 8
    for (int j = 0; j < 32; j++) {
        float a, v;
        compute_av(sh_g[base + j], sh_h[base + j], a, v);
        sh_g[base + j] = a;
        sh_h[base + j] = v;
        S = fmaf(a, S, v);
        A *= a;
    }

    #pragma unroll
    for (int off = 1; off < 32; off <<= 1) {
        float Ap = __shfl_up_sync(0xffffffffu, A, off);
        float Sp = __shfl_up_sync(0xffffffffu, S, off);
        if (lane >= off) { S = fmaf(A, Sp, S); A *= Ap; }
    }
    if (lane == 31) { warpA[w] = A; warpS[w] = S; }

    float Ae = __shfl_up_sync(0xffffffffu, A, 1);
    float Se = __shfl_up_sync(0xffffffffu, S, 1);
    if (lane == 0) { Ae = 1.f; Se = 0.f; }
    __syncthreads();

    float carry = 0.f;
    for (int i = 0; i < w; i++) carry = fmaf(warpA[i], carry, warpS[i]);
    float h = fmaf(Ae, carry, Se);

    // Phase 2: replay with cached (a, v)
    #pragma unroll 8
    for (int j = 0; j < 32; j++) {
        h = fmaf(sh_g[base + j], h, sh_h[base + j]);
        sh_h[base + j] = h;
    }
    __syncthreads();

    for (int l = tid; l < LDIM; l += 256) {
        int tau = back ? (LDIM - 1 - l) : l;
        orow[l] = sh_h[tau + (tau >> 5)];
    }
}

// ---------------------------------------------------------------------------
// Launcher
// ---------------------------------------------------------------------------
extern "C" void kernel_launch(void* const* d_in, const int* in_sizes, int n_in,
                              void* d_out, int out_size) {
    const float* x = (const float*)d_in[0];
    const float* W = (const float*)d_in[1];
    if (n_in >= 2 && in_sizes[0] == MDIM * KDIM && in_sizes[1] != MDIM * KDIM) {
        W = (const float*)d_in[0];
        x = (const float*)d_in[1];
    }
    float* out = (float*)d_out;

    cudaFuncSetAttribute(gemm_mma_kernel,
                         cudaFuncAttributeMaxDynamicSharedMemorySize, GEMM_SMEM);
    cudaFuncSetAttribute(scan_kernel,
                         cudaFuncAttributeMaxDynamicSharedMemorySize,
                         2 * SKEW_SZ * (int)sizeof(float));

    wnorm_kernel<<<MDIM, 128>>>(W);
    xconv_kernel<<<dim3(LDIM / 32, DDIM / 32, BATCH), dim3(32, 8)>>>(x);
    gemm_mma_kernel<<<dim3(MDIM / BM, LDIM / BN, BATCH), 256, GEMM_SMEM>>>();
    scan_kernel<<<BATCH * DDIM, 256, 2 * SKEW_SZ * sizeof(float)>>>(out);
}